// round 5
// baseline (speedup 1.0000x reference)
#include <cuda_runtime.h>

#define NTOK   4096
#define DMODEL 2048
#define NH     16
#define HDIM   128
#define SDIM   64
#define NSLOT  16
#define NUNIT  (NTOK * NH)

#define OUT_STACK_OFF 8388608ll
#define OUT_MASK_OFF  75497472ll

#define KSPLIT 16

__device__ float g_part[(size_t)KSPLIT * NTOK * 48];
__device__ float g_act[(size_t)NTOK * 48];
__device__ float g_k[(size_t)NUNIT * SDIM];
__device__ float g_mo[(size_t)NUNIT * SDIM];

// ---- Kernel 1: logits partials. grid = 32 token-tiles * 16 ksplits, 128 thr.
// tile 128 tok x 48 out, frag 8 tok x 6 out, K slice 128 (chunks of 64).
__global__ void __launch_bounds__(128) k_logits(const float* __restrict__ hid,
                                                const float* __restrict__ Wa) {
    const int tile = blockIdx.x >> 4;
    const int ks   = blockIdx.x & 15;
    const int t0   = tile * 128;
    const int kb   = ks * 128;
    __shared__ float a_sm[128 * 66];
    __shared__ float w_sm[48 * 66];
    const int tid = threadIdx.x;
    const int tg  = tid & 15;        // tok rows tg + 16*tt, tt<8
    const int og  = tid >> 4;        // out cols og*6 .. og*6+5
    float acc[8][6];
#pragma unroll
    for (int i = 0; i < 8; i++)
#pragma unroll
        for (int j = 0; j < 6; j++) acc[i][j] = 0.f;

    for (int kc = 0; kc < 128; kc += 64) {
        __syncthreads();
        for (int i = tid; i < 128 * 64; i += 128) {
            int t = i >> 6, kk = i & 63;
            a_sm[t * 66 + kk] = hid[(size_t)(t0 + t) * DMODEL + kb + kc + kk];
        }
        for (int i = tid; i < 48 * 64; i += 128) {
            int o = i >> 6, kk = i & 63;
            w_sm[o * 66 + kk] = Wa[(size_t)o * DMODEL + kb + kc + kk];
        }
        __syncthreads();
#pragma unroll
        for (int kk = 0; kk < 64; kk += 2) {
            float2 av[8], wv[6];
#pragma unroll
            for (int tt = 0; tt < 8; tt++)
                av[tt] = *(const float2*)&a_sm[(tg + 16 * tt) * 66 + kk];
#pragma unroll
            for (int oc = 0; oc < 6; oc++)
                wv[oc] = *(const float2*)&w_sm[(og * 6 + oc) * 66 + kk];
#pragma unroll
            for (int tt = 0; tt < 8; tt++)
#pragma unroll
                for (int oc = 0; oc < 6; oc++) {
                    acc[tt][oc] = fmaf(av[tt].x, wv[oc].x, acc[tt][oc]);
                    acc[tt][oc] = fmaf(av[tt].y, wv[oc].y, acc[tt][oc]);
                }
        }
    }
#pragma unroll
    for (int tt = 0; tt < 8; tt++) {
        size_t b = ((size_t)ks * NTOK + t0 + tg + 16 * tt) * 48 + og * 6;
#pragma unroll
        for (int oc = 0; oc < 6; oc += 2)
            *(float2*)&g_part[b + oc] = make_float2(acc[tt][oc], acc[tt][oc + 1]);
    }
}

// ---- Kernel 2: reduce partials, softmax over 3 actions.
__global__ void __launch_bounds__(256) k_actsm() {
    const int gid = blockIdx.x * 256 + threadIdx.x;
    const int t = gid >> 4, h = gid & 15;
    float l0 = 0.f, l1 = 0.f, l2 = 0.f;
#pragma unroll
    for (int ks = 0; ks < KSPLIT; ks++) {
        size_t b = ((size_t)ks * NTOK + t) * 48 + h * 3;
        l0 += g_part[b]; l1 += g_part[b + 1]; l2 += g_part[b + 2];
    }
    const float s = 0.08838834764831845f;
    l0 *= s; l1 *= s; l2 *= s;
    float m = fmaxf(l0, fmaxf(l1, l2));
    float e0 = __expf(l0 - m), e1 = __expf(l1 - m), e2 = __expf(l2 - m);
    float inv = 1.f / (e0 + e1 + e2);
    size_t ob = (size_t)t * 48 + h * 3;
    g_act[ob] = e0 * inv; g_act[ob + 1] = e1 * inv; g_act[ob + 2] = e2 * inv;
}

// ---- Kernel 3: k = hidden([65536 x 128]) @ W_down^T. tile 128x64, 8x8 frag.
__global__ void __launch_bounds__(128) k_down(const float* __restrict__ hid,
                                              const float* __restrict__ Wd) {
    const int u0 = blockIdx.x * 128;
    __shared__ float a_sm[128 * 34];
    __shared__ float w_sm[64 * 34];
    const int tid = threadIdx.x;
    const int rg = tid & 15;    // rows rg + 16*rr
    const int cg = tid >> 4;    // cols cg*8 .. cg*8+7
    float acc[8][8];
#pragma unroll
    for (int i = 0; i < 8; i++)
#pragma unroll
        for (int j = 0; j < 8; j++) acc[i][j] = 0.f;

    for (int kc = 0; kc < 128; kc += 32) {
        __syncthreads();
        for (int i = tid; i < 128 * 32; i += 128) {
            int r = i >> 5, kk = i & 31;
            a_sm[r * 34 + kk] = hid[(size_t)(u0 + r) * HDIM + kc + kk];
        }
        for (int i = tid; i < 64 * 32; i += 128) {
            int c = i >> 5, kk = i & 31;
            w_sm[c * 34 + kk] = Wd[(size_t)c * HDIM + kc + kk];
        }
        __syncthreads();
#pragma unroll
        for (int kk = 0; kk < 32; kk += 2) {
            float2 av[8], wv[8];
#pragma unroll
            for (int rr = 0; rr < 8; rr++)
                av[rr] = *(const float2*)&a_sm[(rg + 16 * rr) * 34 + kk];
#pragma unroll
            for (int cc = 0; cc < 8; cc++)
                wv[cc] = *(const float2*)&w_sm[(cg * 8 + cc) * 34 + kk];
#pragma unroll
            for (int rr = 0; rr < 8; rr++)
#pragma unroll
                for (int cc = 0; cc < 8; cc++) {
                    acc[rr][cc] = fmaf(av[rr].x, wv[cc].x, acc[rr][cc]);
                    acc[rr][cc] = fmaf(av[rr].y, wv[cc].y, acc[rr][cc]);
                }
        }
    }
#pragma unroll
    for (int rr = 0; rr < 8; rr++) {
        size_t b = (size_t)(u0 + rg + 16 * rr) * SDIM + cg * 8;
        *(float4*)&g_k[b]     = make_float4(acc[rr][0], acc[rr][1], acc[rr][2], acc[rr][3]);
        *(float4*)&g_k[b + 4] = make_float4(acc[rr][4], acc[rr][5], acc[rr][6], acc[rr][7]);
    }
}

// ---- Kernel 4: stack blend via linearity. 4 units/block, parallel tail.
__global__ void __launch_bounds__(256) k_stack(const float* __restrict__ stk,
                                               const float* __restrict__ msk,
                                               const float* __restrict__ Wg,
                                               float* __restrict__ out) {
    __shared__ float4 s4[4 * 256];      // [unit][slot][dv] -- OLD stack
    __shared__ float red[4][17];        // S_j per unit, [16]=dot(k,g)
    __shared__ float msm[64];
    __shared__ float acts[12];
    const int tid  = threadIdx.x;
    const int slot = tid >> 4;
    const int dv   = tid & 15;
    const int u0   = blockIdx.x * 4;

    if (tid < 64) msm[tid] = msk[(size_t)u0 * 16 + tid];
    if (tid < 12) {
        int i = tid / 3, c = tid - i * 3;
        int u = u0 + i;
        acts[tid] = g_act[(size_t)(u >> 4) * 48 + (u & 15) * 3 + c];
    }
    const float4 g4 = ((const float4*)Wg)[dv];
    const float4* gs = (const float4*)stk + (size_t)u0 * 256;
    float4 r4[4];
#pragma unroll
    for (int i = 0; i < 4; i++) { r4[i] = gs[tid + 256 * i]; s4[tid + 256 * i] = r4[i]; }
    float4 k4[4];
    if (slot == 0) {
#pragma unroll
        for (int i = 0; i < 4; i++)
            k4[i] = ((const float4*)g_k)[(size_t)(u0 + i) * 16 + dv];
    }

    // S_j = dot(old row, g): reduce over dv (16-lane groups)
#pragma unroll
    for (int i = 0; i < 4; i++) {
        float p = r4[i].x * g4.x + r4[i].y * g4.y + r4[i].z * g4.z + r4[i].w * g4.w;
        p += __shfl_xor_sync(0xffffffffu, p, 8);
        p += __shfl_xor_sync(0xffffffffu, p, 4);
        p += __shfl_xor_sync(0xffffffffu, p, 2);
        p += __shfl_xor_sync(0xffffffffu, p, 1);
        if (dv == 0) red[i][slot] = p;
    }
    if (slot == 0) {
#pragma unroll
        for (int i = 0; i < 4; i++) {
            float p = k4[i].x * g4.x + k4[i].y * g4.y + k4[i].z * g4.z + k4[i].w * g4.w;
            p += __shfl_xor_sync(0x0000ffffu, p, 8);
            p += __shfl_xor_sync(0x0000ffffu, p, 4);
            p += __shfl_xor_sync(0x0000ffffu, p, 2);
            p += __shfl_xor_sync(0x0000ffffu, p, 1);
            if (dv == 0) red[i][16] = p;
        }
    }
    __syncthreads();

    // blend -> new_stack, straight to gmem (s4 keeps OLD values)
    float4* os = (float4*)(out + OUT_STACK_OFF) + (size_t)u0 * 256;
#pragma unroll
    for (int i = 0; i < 4; i++) {
        float ap = acts[i * 3], apop = acts[i * 3 + 1], an = acts[i * 3 + 2];
        float4 prev = (slot == 0) ? k4[i] : s4[i * 256 + tid - 16];
        float4 nxt  = (slot == 15) ? make_float4(0.f, 0.f, 0.f, 0.f)
                                   : s4[i * 256 + tid + 16];
        float4 c = r4[i];
        float4 nw;
        nw.x = ap * prev.x + apop * nxt.x + an * c.x;
        nw.y = ap * prev.y + apop * nxt.y + an * c.y;
        nw.z = ap * prev.z + apop * nxt.z + an * c.z;
        nw.w = ap * prev.w + apop * nxt.w + an * c.w;
        os[i * 256 + tid] = nw;
    }

    // mask output: 64 threads, one element each
    if (tid < 64) {
        const int q2 = tid >> 4, j = tid & 15;
        float ap = acts[q2 * 3], apop = acts[q2 * 3 + 1], an = acts[q2 * 3 + 2];
        float pm = (j == 0) ? 1.f : msm[q2 * 16 + j - 1];
        float qm = (j < 15) ? msm[q2 * 16 + j + 1] : 0.f;
        out[OUT_MASK_OFF + (size_t)u0 * 16 + tid] =
            ap * pm + apop * qm + an * msm[q2 * 16 + j];
    }

    // tail over ALL 256 threads: unit q = tid>>6, scalar d = tid&63
    {
        const int q = tid >> 6, d = tid & 63;
        float ap = acts[q * 3], apop = acts[q * 3 + 1], an = acts[q * 3 + 2];
        float kdot = red[q][16];
        float sc[16], mx = -3.4e38f;
#pragma unroll
        for (int j = 0; j < 16; j++) {
            float pm = (j == 0) ? 1.f : msm[q * 16 + j - 1];
            float qm = (j < 15) ? msm[q * 16 + j + 1] : 0.f;
            float mk = ap * pm + apop * qm + an * msm[q * 16 + j];
            float Sm1 = (j == 0) ? kdot : red[q][j - 1];
            float Sp1 = (j < 15) ? red[q][j + 1] : 0.f;
            float v = ap * Sm1 + apop * Sp1 + an * red[q][j] + (1.f - mk) * (-1e9f);
            sc[j] = v;
            mx = fmaxf(mx, v);
        }
        float ss = 0.f;
#pragma unroll
        for (int j = 0; j < 16; j++) { sc[j] = __expf(sc[j] - mx); ss += sc[j]; }
        float inv = 1.f / ss;

        const float* s = (const float*)s4 + q * 1024;   // [slot][64]
        float mo = ap * sc[0] * inv * g_k[(size_t)(u0 + q) * 64 + d];
#pragma unroll
        for (int m = 0; m < 16; m++) {
            float wp1 = (m < 15) ? sc[m + 1] : 0.f;
            float wm1 = (m > 0) ? sc[m - 1] : 0.f;
            float cm = (ap * wp1 + apop * wm1 + an * sc[m]) * inv;
            mo = fmaf(cm, s[m * 64 + d], mo);
        }
        g_mo[(size_t)(u0 + q) * 64 + d] = mo;
    }
}

// ---- Kernel 5: out = res_weight * (mo @ W_up^T) + hidden. 128x128 tile, 8x8 frag.
__global__ void __launch_bounds__(256) k_up(const float* __restrict__ hid,
                                            const float* __restrict__ Wu,
                                            const float* __restrict__ rsw,
                                            float* __restrict__ out) {
    const int u0 = blockIdx.x * 128;
    __shared__ float a_sm[128 * 34];
    __shared__ float w_sm[128 * 34];
    const int tid = threadIdx.x;
    const int rg = tid & 15;    // rows rg + 16*rr
    const int cg = tid >> 4;    // cols cg*8 .. cg*8+7
    float acc[8][8];
#pragma unroll
    for (int i = 0; i < 8; i++)
#pragma unroll
        for (int j = 0; j < 8; j++) acc[i][j] = 0.f;

    for (int kc = 0; kc < 64; kc += 32) {
        __syncthreads();
        for (int i = tid; i < 128 * 32; i += 256) {
            int r = i >> 5, kk = i & 31;
            a_sm[r * 34 + kk] = g_mo[(size_t)(u0 + r) * SDIM + kc + kk];
        }
        for (int i = tid; i < 128 * 32; i += 256) {
            int c = i >> 5, kk = i & 31;
            w_sm[c * 34 + kk] = Wu[(size_t)c * SDIM + kc + kk];
        }
        __syncthreads();
#pragma unroll
        for (int kk = 0; kk < 32; kk += 2) {
            float2 av[8], wv[8];
#pragma unroll
            for (int rr = 0; rr < 8; rr++)
                av[rr] = *(const float2*)&a_sm[(rg + 16 * rr) * 34 + kk];
#pragma unroll
            for (int cc = 0; cc < 8; cc++)
                wv[cc] = *(const float2*)&w_sm[(cg * 8 + cc) * 34 + kk];
#pragma unroll
            for (int rr = 0; rr < 8; rr++)
#pragma unroll
                for (int cc = 0; cc < 8; cc++) {
                    acc[rr][cc] = fmaf(av[rr].x, wv[cc].x, acc[rr][cc]);
                    acc[rr][cc] = fmaf(av[rr].y, wv[cc].y, acc[rr][cc]);
                }
        }
    }
    const float rw = rsw[0];
#pragma unroll
    for (int rr = 0; rr < 8; rr++) {
        size_t b = (size_t)(u0 + rg + 16 * rr) * HDIM + cg * 8;
        float4 h0 = *(const float4*)&hid[b];
        float4 h1 = *(const float4*)&hid[b + 4];
        float4 o0 = make_float4(fmaf(rw, acc[rr][0], h0.x), fmaf(rw, acc[rr][1], h0.y),
                                fmaf(rw, acc[rr][2], h0.z), fmaf(rw, acc[rr][3], h0.w));
        float4 o1 = make_float4(fmaf(rw, acc[rr][4], h1.x), fmaf(rw, acc[rr][5], h1.y),
                                fmaf(rw, acc[rr][6], h1.z), fmaf(rw, acc[rr][7], h1.w));
        *(float4*)&out[b] = o0;
        *(float4*)&out[b + 4] = o1;
    }
}

extern "C" void kernel_launch(void* const* d_in, const int* in_sizes, int n_in,
                              void* d_out, int out_size) {
    const float* hid = (const float*)d_in[0];
    const float* stk = (const float*)d_in[1];
    const float* msk = (const float*)d_in[2];
    const float* Wa  = (const float*)d_in[3];
    const float* Wg  = (const float*)d_in[4];
    const float* Wd  = (const float*)d_in[5];
    const float* Wu  = (const float*)d_in[6];
    const float* rsw = (const float*)d_in[7];
    float* out = (float*)d_out;

    k_logits<<<512, 128>>>(hid, Wa);
    k_actsm<<<256, 256>>>();
    k_down<<<512, 128>>>(hid, Wd);
    k_stack<<<16384, 256>>>(stk, msk, Wg, out);
    k_up<<<512, 256>>>(hid, Wu, rsw, out);
}

// round 6
// speedup vs baseline: 1.1374x; 1.1374x over previous
#include <cuda_runtime.h>

#define NTOK   4096
#define DMODEL 2048
#define NH     16
#define HDIM   128
#define SDIM   64
#define NSLOT  16
#define NUNIT  (NTOK * NH)

#define OUT_STACK_OFF 8388608ll
#define OUT_MASK_OFF  75497472ll

__device__ float g_part[8ll * NTOK * 48];
__device__ float g_act[(size_t)NTOK * 48];
__device__ float g_k[(size_t)NUNIT * SDIM];
__device__ float g_mo[(size_t)NUNIT * SDIM];

// ---- Kernel 1: logits partials (split-K 8). 64-tok tile, 256 thr.
__global__ void __launch_bounds__(256) k_logits(const float* __restrict__ hid,
                                                const float* __restrict__ Wa) {
    const int tile = blockIdx.x >> 3;
    const int ks   = blockIdx.x & 7;
    const int t0   = tile * 64;
    const int kb   = ks * 256;
    __shared__ float a_sm[64 * 68];
    __shared__ float w_sm[48 * 68];
    const int tid = threadIdx.x;
    const int tg  = tid & 15;
    const int og  = tid >> 4;
    float acc[4][3];
#pragma unroll
    for (int i = 0; i < 4; i++)
#pragma unroll
        for (int j = 0; j < 3; j++) acc[i][j] = 0.f;

    for (int kc = 0; kc < 256; kc += 64) {
        __syncthreads();
        for (int i = tid; i < 64 * 64; i += 256) {
            int t = i >> 6, kk = i & 63;
            a_sm[t * 68 + kk] = hid[(size_t)(t0 + t) * DMODEL + kb + kc + kk];
        }
        for (int i = tid; i < 48 * 64; i += 256) {
            int o = i >> 6, kk = i & 63;
            w_sm[o * 68 + kk] = Wa[(size_t)o * DMODEL + kb + kc + kk];
        }
        __syncthreads();
#pragma unroll
        for (int kk = 0; kk < 64; kk += 4) {
            float4 av[4], wv[3];
#pragma unroll
            for (int tt = 0; tt < 4; tt++)
                av[tt] = *(const float4*)&a_sm[(tg + 16 * tt) * 68 + kk];
#pragma unroll
            for (int oc = 0; oc < 3; oc++)
                wv[oc] = *(const float4*)&w_sm[(og * 3 + oc) * 68 + kk];
#pragma unroll
            for (int tt = 0; tt < 4; tt++)
#pragma unroll
                for (int oc = 0; oc < 3; oc++) {
                    acc[tt][oc] = fmaf(av[tt].x, wv[oc].x, acc[tt][oc]);
                    acc[tt][oc] = fmaf(av[tt].y, wv[oc].y, acc[tt][oc]);
                    acc[tt][oc] = fmaf(av[tt].z, wv[oc].z, acc[tt][oc]);
                    acc[tt][oc] = fmaf(av[tt].w, wv[oc].w, acc[tt][oc]);
                }
        }
    }
#pragma unroll
    for (int tt = 0; tt < 4; tt++)
#pragma unroll
        for (int oc = 0; oc < 3; oc++)
            g_part[((size_t)ks * NTOK + t0 + tg + 16 * tt) * 48 + og * 3 + oc] =
                acc[tt][oc];
}

// ---- Kernel 2: reduce partials, softmax over 3 actions.
__global__ void __launch_bounds__(256) k_actsm() {
    const int gid = blockIdx.x * 256 + threadIdx.x;
    const int t = gid >> 4, h = gid & 15;
    float l0 = 0.f, l1 = 0.f, l2 = 0.f;
#pragma unroll
    for (int ks = 0; ks < 8; ks++) {
        size_t b = ((size_t)ks * NTOK + t) * 48 + h * 3;
        l0 += g_part[b]; l1 += g_part[b + 1]; l2 += g_part[b + 2];
    }
    const float s = 0.08838834764831845f;
    l0 *= s; l1 *= s; l2 *= s;
    float m = fmaxf(l0, fmaxf(l1, l2));
    float e0 = __expf(l0 - m), e1 = __expf(l1 - m), e2 = __expf(l2 - m);
    float inv = 1.f / (e0 + e1 + e2);
    size_t ob = (size_t)t * 48 + h * 3;
    g_act[ob] = e0 * inv; g_act[ob + 1] = e1 * inv; g_act[ob + 2] = e2 * inv;
}

// ---- Kernel 3: k = hidden([65536 x 128]) @ W_down^T -> [65536 x 64].
__global__ void __launch_bounds__(256) k_down(const float* __restrict__ hid,
                                              const float* __restrict__ Wd) {
    const int u0 = blockIdx.x * 128;
    __shared__ float a_sm[128 * 36];
    __shared__ float w_sm[64 * 36];
    const int tid = threadIdx.x;
    const int rg = tid & 15;
    const int cg = tid >> 4;
    float acc[8][4];
#pragma unroll
    for (int i = 0; i < 8; i++)
#pragma unroll
        for (int j = 0; j < 4; j++) acc[i][j] = 0.f;

    for (int kc = 0; kc < 128; kc += 32) {
        __syncthreads();
        for (int i = tid; i < 128 * 32; i += 256) {
            int r = i >> 5, kk = i & 31;
            a_sm[r * 36 + kk] = hid[(size_t)(u0 + r) * HDIM + kc + kk];
        }
        for (int i = tid; i < 64 * 32; i += 256) {
            int c = i >> 5, kk = i & 31;
            w_sm[c * 36 + kk] = Wd[(size_t)c * HDIM + kc + kk];
        }
        __syncthreads();
#pragma unroll
        for (int kk = 0; kk < 32; kk += 4) {
            float4 av[8], wv[4];
#pragma unroll
            for (int rr = 0; rr < 8; rr++)
                av[rr] = *(const float4*)&a_sm[(rg + 16 * rr) * 36 + kk];
#pragma unroll
            for (int cc = 0; cc < 4; cc++)
                wv[cc] = *(const float4*)&w_sm[(cg * 4 + cc) * 36 + kk];
#pragma unroll
            for (int rr = 0; rr < 8; rr++)
#pragma unroll
                for (int cc = 0; cc < 4; cc++) {
                    acc[rr][cc] = fmaf(av[rr].x, wv[cc].x, acc[rr][cc]);
                    acc[rr][cc] = fmaf(av[rr].y, wv[cc].y, acc[rr][cc]);
                    acc[rr][cc] = fmaf(av[rr].z, wv[cc].z, acc[rr][cc]);
                    acc[rr][cc] = fmaf(av[rr].w, wv[cc].w, acc[rr][cc]);
                }
        }
    }
#pragma unroll
    for (int rr = 0; rr < 8; rr++) {
        float4 v = make_float4(acc[rr][0], acc[rr][1], acc[rr][2], acc[rr][3]);
        *(float4*)&g_k[(size_t)(u0 + rg + 16 * rr) * SDIM + cg * 4] = v;
    }
}

// ---- Kernel 4: stack blend, warp-per-unit softmax -> coefficients.
__global__ void __launch_bounds__(256) k_stack(const float* __restrict__ stk,
                                               const float* __restrict__ msk,
                                               const float* __restrict__ Wg,
                                               float* __restrict__ out) {
    __shared__ float4 s4[4 * 256];      // old stack [unit][slot][dv]
    __shared__ float4 ksm4[64];         // k vectors [unit][dv]
    __shared__ float red[4][17];        // S_j, [16]=dot(k,g)
    __shared__ float coef[4][17];       // blend coefs, [16]=coef of k
    __shared__ float msm[64];
    __shared__ float acts[12];
    const int tid  = threadIdx.x;
    const int slot = tid >> 4;
    const int dv   = tid & 15;
    const int u0   = blockIdx.x * 4;

    if (tid < 64) {
        msm[tid] = msk[(size_t)u0 * 16 + tid];
        ksm4[tid] = ((const float4*)g_k)[(size_t)u0 * 16 + tid];
    }
    if (tid < 12) {
        int i = tid / 3, c = tid - i * 3;
        int u = u0 + i;
        acts[tid] = g_act[(size_t)(u >> 4) * 48 + (u & 15) * 3 + c];
    }
    const float4 g4 = ((const float4*)Wg)[dv];
    const float4* gs = (const float4*)stk + (size_t)u0 * 256;
    float4 r4[4];
#pragma unroll
    for (int i = 0; i < 4; i++) { r4[i] = gs[tid + 256 * i]; s4[tid + 256 * i] = r4[i]; }

    // S_j = dot(old row, g), reduced over the 16 dv lanes
#pragma unroll
    for (int i = 0; i < 4; i++) {
        float p = r4[i].x * g4.x + r4[i].y * g4.y + r4[i].z * g4.z + r4[i].w * g4.w;
        p += __shfl_xor_sync(0xffffffffu, p, 8);
        p += __shfl_xor_sync(0xffffffffu, p, 4);
        p += __shfl_xor_sync(0xffffffffu, p, 2);
        p += __shfl_xor_sync(0xffffffffu, p, 1);
        if (dv == 0) red[i][slot] = p;
    }
    // kdot: threads 0..63 hold k[unit=tid>>4][dv] (from registers via reload)
    if (tid < 64) {
        float4 kv = ((const float4*)g_k)[(size_t)u0 * 16 + tid];
        float p = kv.x * g4.x + kv.y * g4.y + kv.z * g4.z + kv.w * g4.w;
        p += __shfl_xor_sync(0xffffffffu, p, 8);
        p += __shfl_xor_sync(0xffffffffu, p, 4);
        p += __shfl_xor_sync(0xffffffffu, p, 2);
        p += __shfl_xor_sync(0xffffffffu, p, 1);
        if ((tid & 15) == 0) red[tid >> 4][16] = p;
    }
    __syncthreads();

    // blend -> new_stack straight to gmem (s4 keeps OLD rows)
    float4* os = (float4*)(out + OUT_STACK_OFF) + (size_t)u0 * 256;
#pragma unroll
    for (int i = 0; i < 4; i++) {
        float ap = acts[i * 3], apop = acts[i * 3 + 1], an = acts[i * 3 + 2];
        float4 prev = (slot == 0) ? ksm4[i * 16 + dv] : s4[i * 256 + tid - 16];
        float4 nxt  = (slot == 15) ? make_float4(0.f, 0.f, 0.f, 0.f)
                                   : s4[i * 256 + tid + 16];
        float4 c = r4[i];
        float4 nw;
        nw.x = ap * prev.x + apop * nxt.x + an * c.x;
        nw.y = ap * prev.y + apop * nxt.y + an * c.y;
        nw.z = ap * prev.z + apop * nxt.z + an * c.z;
        nw.w = ap * prev.w + apop * nxt.w + an * c.w;
        os[i * 256 + tid] = nw;
    }

    // new mask: 64 threads, one element each
    if (tid < 64) {
        const int q2 = tid >> 4, j = tid & 15;
        float ap = acts[q2 * 3], apop = acts[q2 * 3 + 1], an = acts[q2 * 3 + 2];
        float pm = (j == 0) ? 1.f : msm[q2 * 16 + j - 1];
        float qm = (j < 15) ? msm[q2 * 16 + j + 1] : 0.f;
        out[OUT_MASK_OFF + (size_t)u0 * 16 + tid] =
            ap * pm + apop * qm + an * msm[q2 * 16 + j];
    }

    // warps 0-3: unit q softmax -> blend coefficients (lane j owns slot j,
    // lanes 16-31 mirror j = lane&15; reductions stay in 16-lane halves).
    const int wq = tid >> 5;
    if (wq < 4) {
        const int q = wq;
        const int j = tid & 15;
        const int lane = tid & 31;
        float ap = acts[q * 3], apop = acts[q * 3 + 1], an = acts[q * 3 + 2];
        float pm = (j == 0) ? 1.f : msm[q * 16 + j - 1];
        float qm = (j < 15) ? msm[q * 16 + j + 1] : 0.f;
        float mk = ap * pm + apop * qm + an * msm[q * 16 + j];
        float Sm1 = (j == 0) ? red[q][16] : red[q][j - 1];
        float Sp1 = (j < 15) ? red[q][j + 1] : 0.f;
        float v = ap * Sm1 + apop * Sp1 + an * red[q][j] + (1.f - mk) * (-1e9f);
        float mx = v;
        mx = fmaxf(mx, __shfl_xor_sync(0xffffffffu, mx, 8));
        mx = fmaxf(mx, __shfl_xor_sync(0xffffffffu, mx, 4));
        mx = fmaxf(mx, __shfl_xor_sync(0xffffffffu, mx, 2));
        mx = fmaxf(mx, __shfl_xor_sync(0xffffffffu, mx, 1));
        float e = __expf(v - mx);
        float ss = e;
        ss += __shfl_xor_sync(0xffffffffu, ss, 8);
        ss += __shfl_xor_sync(0xffffffffu, ss, 4);
        ss += __shfl_xor_sync(0xffffffffu, ss, 2);
        ss += __shfl_xor_sync(0xffffffffu, ss, 1);
        float wgt = e / ss;
        float wp1 = __shfl_down_sync(0xffffffffu, wgt, 1);
        if (j == 15) wp1 = 0.f;
        float wm1 = __shfl_up_sync(0xffffffffu, wgt, 1);
        if (j == 0) wm1 = 0.f;
        if (lane < 16) {
            coef[q][j] = ap * wp1 + apop * wm1 + an * wgt;
            if (lane == 0) coef[q][16] = ap * wgt;   // coefficient of k
        }
    }
    __syncthreads();

    // mo = coef_k * k + sum_m coef_m * old_m   (broadcast coefs, no arrays)
    {
        const int q = tid >> 6, d = tid & 63;
        const float* ks = (const float*)ksm4 + q * 64;
        const float* s  = (const float*)s4 + q * 1024;
        float mo = coef[q][16] * ks[d];
#pragma unroll
        for (int m = 0; m < 16; m++) mo = fmaf(coef[q][m], s[m * 64 + d], mo);
        g_mo[(size_t)(u0 + q) * 64 + d] = mo;
    }
}

// ---- Kernel 5: out = res_weight * (mo @ W_up^T) + hidden. 64x128 tile, 4x8 frag.
__global__ void __launch_bounds__(256) k_up(const float* __restrict__ hid,
                                            const float* __restrict__ Wu,
                                            const float* __restrict__ rsw,
                                            float* __restrict__ out) {
    const int u0 = blockIdx.x * 64;
    __shared__ float a_sm[64 * 36];
    __shared__ float w_sm[128 * 36];
    const int tid = threadIdx.x;
    const int rg = tid & 15;
    const int cg = tid >> 4;
    float acc[4][8];
#pragma unroll
    for (int i = 0; i < 4; i++)
#pragma unroll
        for (int j = 0; j < 8; j++) acc[i][j] = 0.f;

    for (int kc = 0; kc < 64; kc += 32) {
        __syncthreads();
        for (int i = tid; i < 64 * 32; i += 256) {
            int r = i >> 5, kk = i & 31;
            a_sm[r * 36 + kk] = g_mo[(size_t)(u0 + r) * SDIM + kc + kk];
        }
        for (int i = tid; i < 128 * 32; i += 256) {
            int c = i >> 5, kk = i & 31;
            w_sm[c * 36 + kk] = Wu[(size_t)c * SDIM + kc + kk];
        }
        __syncthreads();
#pragma unroll
        for (int kk = 0; kk < 32; kk += 4) {
            float4 av[4], wv[8];
#pragma unroll
            for (int rr = 0; rr < 4; rr++)
                av[rr] = *(const float4*)&a_sm[(rg + 16 * rr) * 36 + kk];
#pragma unroll
            for (int cc = 0; cc < 8; cc++)
                wv[cc] = *(const float4*)&w_sm[(cg * 8 + cc) * 36 + kk];
#pragma unroll
            for (int rr = 0; rr < 4; rr++)
#pragma unroll
                for (int cc = 0; cc < 8; cc++) {
                    acc[rr][cc] = fmaf(av[rr].x, wv[cc].x, acc[rr][cc]);
                    acc[rr][cc] = fmaf(av[rr].y, wv[cc].y, acc[rr][cc]);
                    acc[rr][cc] = fmaf(av[rr].z, wv[cc].z, acc[rr][cc]);
                    acc[rr][cc] = fmaf(av[rr].w, wv[cc].w, acc[rr][cc]);
                }
        }
    }
    const float rw = rsw[0];
#pragma unroll
    for (int rr = 0; rr < 4; rr++) {
        size_t b = (size_t)(u0 + rg + 16 * rr) * HDIM + cg * 8;
        float4 h0 = *(const float4*)&hid[b];
        float4 h1 = *(const float4*)&hid[b + 4];
        float4 o0 = make_float4(fmaf(rw, acc[rr][0], h0.x), fmaf(rw, acc[rr][1], h0.y),
                                fmaf(rw, acc[rr][2], h0.z), fmaf(rw, acc[rr][3], h0.w));
        float4 o1 = make_float4(fmaf(rw, acc[rr][4], h1.x), fmaf(rw, acc[rr][5], h1.y),
                                fmaf(rw, acc[rr][6], h1.z), fmaf(rw, acc[rr][7], h1.w));
        *(float4*)&out[b] = o0;
        *(float4*)&out[b + 4] = o1;
    }
}

extern "C" void kernel_launch(void* const* d_in, const int* in_sizes, int n_in,
                              void* d_out, int out_size) {
    const float* hid = (const float*)d_in[0];
    const float* stk = (const float*)d_in[1];
    const float* msk = (const float*)d_in[2];
    const float* Wa  = (const float*)d_in[3];
    const float* Wg  = (const float*)d_in[4];
    const float* Wd  = (const float*)d_in[5];
    const float* Wu  = (const float*)d_in[6];
    const float* rsw = (const float*)d_in[7];
    float* out = (float*)d_out;

    k_logits<<<512, 256>>>(hid, Wa);
    k_actsm<<<256, 256>>>();
    k_down<<<512, 256>>>(hid, Wd);
    k_stack<<<16384, 256>>>(stk, msk, Wg, out);
    k_up<<<1024, 256>>>(hid, Wu, rsw, out);
}